// round 17
// baseline (speedup 1.0000x reference)
#include <cuda_runtime.h>
#include <cuda_bf16.h>

// CRF NLL, B x T x K=9 (START=7, STOP=8), 7 live states.
// ONE kernel, 2B blocks:
//  even block 2b : sentence b's 32 operator chunks (C=T/32). 16 groups x 8
//                  lanes; each group evolves TWO chunks (2g, 2g+1) at once —
//                  two independent FFMA2 chains share one register copy of
//                  the exp(trans) matrix, doubling per-thread ILP to cover
//                  the ~120cyc/step dependency chain (measured: occ 24%,
//                  issue 29% -> latency-bound). Operators land in SMEM;
//                  warp-0 lanes 0..7 fold them in-block, atomicAdd(+fwd).
//  odd block 2b+1: gold path score for sentence b; atomicAdd(-gold).
// Done-counter across 2B blocks writes the mean.

#define NCH 32
#define NS  7
#define KK  9

typedef unsigned long long ull;

__device__ float g_accum = 0.f;
__device__ int   g_done  = 0;

__device__ __forceinline__ ull pk2(float x, float y) {
    ull d; asm("mov.b64 %0, {%1,%2};" : "=l"(d) : "f"(x), "f"(y)); return d;
}
__device__ __forceinline__ void upk2(ull d, float& x, float& y) {
    asm("mov.b64 {%0,%1}, %2;" : "=f"(x), "=f"(y) : "l"(d));
}
__device__ __forceinline__ ull ffma2(ull a, ull b, ull c) {
    ull d; asm("fma.rn.f32x2 %0, %1, %2, %3;" : "=l"(d) : "l"(a), "l"(b), "l"(c));
    return d;
}
__device__ __forceinline__ ull fmul2(ull a, ull b) {
    ull d; asm("mul.rn.f32x2 %0, %1, %2;" : "=l"(d) : "l"(a), "l"(b)); return d;
}

// One operator step for one chain: v' = diag(e) * ET * v, via packed f32x2.
// etp layout: row pairs (0,1),(2,3),(4,5),(6,6).
__device__ __forceinline__ void op_step(
    const ull (&etp)[4][NS], float (&v)[NS],
    ull ep0, ull ep1, ull ep2, ull ep3, bool act)
{
    ull dv0 = pk2(v[0], v[0]);
    ull dv1 = pk2(v[1], v[1]);
    ull dv2 = pk2(v[2], v[2]);
    ull dv3 = pk2(v[3], v[3]);
    ull dv4 = pk2(v[4], v[4]);
    ull dv5 = pk2(v[5], v[5]);
    ull dv6 = pk2(v[6], v[6]);

    ull a0 = fmul2(etp[0][0], dv0);
    ull a1 = fmul2(etp[1][0], dv0);
    ull a2 = fmul2(etp[2][0], dv0);
    ull a3 = fmul2(etp[3][0], dv0);
    a0 = ffma2(etp[0][1], dv1, a0); a1 = ffma2(etp[1][1], dv1, a1);
    a2 = ffma2(etp[2][1], dv1, a2); a3 = ffma2(etp[3][1], dv1, a3);
    a0 = ffma2(etp[0][2], dv2, a0); a1 = ffma2(etp[1][2], dv2, a1);
    a2 = ffma2(etp[2][2], dv2, a2); a3 = ffma2(etp[3][2], dv2, a3);
    a0 = ffma2(etp[0][3], dv3, a0); a1 = ffma2(etp[1][3], dv3, a1);
    a2 = ffma2(etp[2][3], dv3, a2); a3 = ffma2(etp[3][3], dv3, a3);
    a0 = ffma2(etp[0][4], dv4, a0); a1 = ffma2(etp[1][4], dv4, a1);
    a2 = ffma2(etp[2][4], dv4, a2); a3 = ffma2(etp[3][4], dv4, a3);
    a0 = ffma2(etp[0][5], dv5, a0); a1 = ffma2(etp[1][5], dv5, a1);
    a2 = ffma2(etp[2][5], dv5, a2); a3 = ffma2(etp[3][5], dv5, a3);
    a0 = ffma2(etp[0][6], dv6, a0); a1 = ffma2(etp[1][6], dv6, a1);
    a2 = ffma2(etp[2][6], dv6, a2); a3 = ffma2(etp[3][6], dv6, a3);

    a0 = fmul2(a0, ep0); a1 = fmul2(a1, ep1);
    a2 = fmul2(a2, ep2); a3 = fmul2(a3, ep3);

    float n0, n1, n2, n3, n4, n5, n6, dead;
    upk2(a0, n0, n1); upk2(a1, n2, n3);
    upk2(a2, n4, n5); upk2(a3, n6, dead);
    v[0] = act ? n0 : v[0];
    v[1] = act ? n1 : v[1];
    v[2] = act ? n2 : v[2];
    v[3] = act ? n3 : v[3];
    v[4] = act ? n4 : v[4];
    v[5] = act ? n5 : v[5];
    v[6] = act ? n6 : v[6];
}

__device__ __forceinline__ void rescale(float (&v)[NS], float& csc)
{
    float mm = v[0];
    #pragma unroll
    for (int j = 1; j < NS; j++) mm = fmaxf(mm, v[j]);
    mm = fmaxf(mm, 1e-30f);
    float inv = __fdividef(1.f, mm);
    #pragma unroll
    for (int j = 0; j < NS; j++) v[j] *= inv;
    csc += __logf(mm);
}

__global__ void __launch_bounds__(128) crf_kernel(
    const float* __restrict__ feats, const float* __restrict__ trans,
    const int* __restrict__ tags, const int* __restrict__ lengths,
    float* __restrict__ out, int B, int T, int C)
{
    __shared__ float s_tr[KK * KK];
    __shared__ float s_et[NS * NS];
    __shared__ float s_op[NCH * 64];   // operator c: [c*64 + s*8 + j]; c*64+7=csmax
    __shared__ float s_red[4];
    int tid = threadIdx.x;
    if (tid < KK * KK) s_tr[tid] = trans[tid];
    __syncthreads();

    int b = blockIdx.x >> 1;
    int L = lengths[b];
    const float* fb = feats + (size_t)b * T * KK;

    if (blockIdx.x & 1) {
        // ================= GOLD block ================================
        const int* tgb = tags + (size_t)b * T;

        float acc = 0.f;
        for (int base = 0; base < L; base += 8 * 128) {
            int tg[8], pv[8];
            #pragma unroll
            for (int i = 0; i < 8; i++) {
                int t = base + tid + (i << 7);
                bool a = t < L;
                tg[i] = a ? __ldg(&tgb[t]) : 0;
                pv[i] = a ? ((t == 0) ? 7 : __ldg(&tgb[t - 1])) : 0;
            }
            #pragma unroll
            for (int i = 0; i < 8; i++) {
                int t = base + tid + (i << 7);
                if (t < L)
                    acc += s_tr[tg[i] * KK + pv[i]] +
                           __ldg(&fb[(size_t)t * KK + tg[i]]);
            }
        }

        int lane = tid & 31, wid = tid >> 5;
        #pragma unroll
        for (int d = 16; d; d >>= 1) acc += __shfl_xor_sync(0xFFFFFFFFu, acc, d);
        if (lane == 0) s_red[wid] = acc;
        __syncthreads();
        if (tid == 0) {
            float tot = s_red[0] + s_red[1] + s_red[2] + s_red[3];
            int last = __ldg(&tgb[L - 1]);
            atomicAdd(&g_accum, -(tot + s_tr[8 * KK + last]));
            __threadfence();
        }
    } else {
        // ============ CHUNK block: dual-chain groups + in-block fold ======
        if (tid < NS * NS) s_et[tid] = __expf(s_tr[(tid / NS) * KK + (tid % NS)]);
        __syncthreads();

        int g = tid >> 3;                   // group 0..15
        int lane = tid & 7;
        unsigned grpw  = (unsigned)(tid & 31) & 24u;
        unsigned mask8 = 0xFFu << grpw;

        int cA = 2 * g, cB = 2 * g + 1;
        int t0A = (cA == 0) ? 1 : cA * C;
        int t1A = min(L, (cA + 1) * C);
        int t0B = cB * C;
        int t1B = min(L, (cB + 1) * C);
        int nA = t1A - t0A; if (nA < 0) nA = 0;
        int nB = t1B - t0B; if (nB < 0) nB = 0;
        int imax = (nA > nB) ? nA : nB;
        bool storeA = (cA == 0) || (cA * C < L);
        bool storeB = (cB * C < L);

        ull etp[4][NS];
        #pragma unroll
        for (int p = 0; p < 4; p++) {
            int j0 = 2 * p, j1 = (2 * p + 1 < NS) ? 2 * p + 1 : NS - 1;
            #pragma unroll
            for (int i = 0; i < NS; i++)
                etp[p][i] = pk2(s_et[j0 * NS + i], s_et[j1 * NS + i]);
        }

        float vA[NS], vB[NS];
        #pragma unroll
        for (int j = 0; j < NS; j++) {
            vA[j] = (j == lane) ? 1.f : 0.f;   // lane7: all zero (unused col)
            vB[j] = (j == lane) ? 1.f : 0.f;
        }
        float cscA = 0.f, cscB = 0.f;

        int rc = 0;
        for (int i = 0; i < imax; ++i) {
            bool aA = i < nA, aB = i < nB;
            float fvA = 0.f, fvB = 0.f;
            if (lane < NS && aA) fvA = __ldg(&fb[(t0A + i) * KK + lane]);
            if (lane < NS && aB) fvB = __ldg(&fb[(t0B + i) * KK + lane]);
            float eA = __expf(fvA);
            float eB = __expf(fvB);

            float eA0 = __shfl_sync(mask8, eA, grpw + 0);
            float eA1 = __shfl_sync(mask8, eA, grpw + 1);
            float eA2 = __shfl_sync(mask8, eA, grpw + 2);
            float eA3 = __shfl_sync(mask8, eA, grpw + 3);
            float eA4 = __shfl_sync(mask8, eA, grpw + 4);
            float eA5 = __shfl_sync(mask8, eA, grpw + 5);
            float eA6 = __shfl_sync(mask8, eA, grpw + 6);
            float eB0 = __shfl_sync(mask8, eB, grpw + 0);
            float eB1 = __shfl_sync(mask8, eB, grpw + 1);
            float eB2 = __shfl_sync(mask8, eB, grpw + 2);
            float eB3 = __shfl_sync(mask8, eB, grpw + 3);
            float eB4 = __shfl_sync(mask8, eB, grpw + 4);
            float eB5 = __shfl_sync(mask8, eB, grpw + 5);
            float eB6 = __shfl_sync(mask8, eB, grpw + 6);

            op_step(etp, vA, pk2(eA0, eA1), pk2(eA2, eA3),
                    pk2(eA4, eA5), pk2(eA6, 0.f), aA);
            op_step(etp, vB, pk2(eB0, eB1), pk2(eB2, eB3),
                    pk2(eB4, eB5), pk2(eB6, 0.f), aB);

            if (++rc == 4) {
                rc = 0;
                rescale(vA, cscA);   // harmless when chain idle:
                rescale(vB, cscB);   // (v,csc) pair invariant under v/m,+log m
            }
        }
        rescale(vA, cscA);
        rescale(vB, cscB);

        // Joint column scaling per chunk.
        float cxA = (lane < NS) ? cscA : -1e30f;
        float cxB = (lane < NS) ? cscB : -1e30f;
        #pragma unroll
        for (int d = 1; d < 8; d <<= 1) {
            cxA = fmaxf(cxA, __shfl_xor_sync(mask8, cxA, d));
            cxB = fmaxf(cxB, __shfl_xor_sync(mask8, cxB, d));
        }
        float wA = __expf(cscA - cxA);
        float wB = __expf(cscB - cxB);

        if (lane < NS) {
            if (storeA) {
                #pragma unroll
                for (int j = 0; j < NS; j++)
                    s_op[cA * 64 + lane * 8 + j] = vA[j] * wA;
            }
            if (storeB) {
                #pragma unroll
                for (int j = 0; j < NS; j++)
                    s_op[cB * 64 + lane * 8 + j] = vB[j] * wB;
            }
        }
        if (lane == 0) {
            if (storeA) s_op[cA * 64 + 7] = cxA;
            if (storeB) s_op[cB * 64 + 7] = cxB;
        }
        __syncthreads();

        // ---------------- in-block fold: warp 0, lanes 0..7 ---------------
        if (tid < 8) {
            const unsigned m8 = 0xFFu;
            float fj = (tid < NS) ? __ldg(&fb[tid]) : 0.f;
            float x = (tid < NS) ? (s_tr[tid * KK + 7] + fj) : -1e30f;
            float m = x;
            #pragma unroll
            for (int d = 1; d < 8; d <<= 1)
                m = fmaxf(m, __shfl_xor_sync(m8, m, d));
            float v = (tid < NS) ? __expf(x - m) : 0.f;
            float sc = m;

            for (int cc = 0; cc < NCH && (cc == 0 || cc * C < L); ++cc) {
                float csmax = s_op[cc * 64 + 7];
                float n = 0.f;
                #pragma unroll
                for (int s = 0; s < NS; ++s) {
                    float vs = __shfl_sync(m8, v, s);
                    n = fmaf(s_op[cc * 64 + s * 8 + tid], vs, n);
                }
                if (tid == 7) n = -1e30f;
                float mm = n;
                #pragma unroll
                for (int d = 1; d < 8; d <<= 1)
                    mm = fmaxf(mm, __shfl_xor_sync(m8, mm, d));
                mm = fmaxf(mm, 1e-30f);
                v = (tid < NS) ? n * __fdividef(1.f, mm) : 0.f;
                sc += csmax + __logf(mm);
            }

            float term = (tid < NS) ? v * __expf(s_tr[8 * KK + tid]) : 0.f;
            #pragma unroll
            for (int d = 1; d < 8; d <<= 1)
                term += __shfl_xor_sync(m8, term, d);
            float fwd = sc + __logf(term);
            if (tid == 0) {
                atomicAdd(&g_accum, fwd);
                __threadfence();
            }
        }
    }

    // ---------------- completion counter over all 2B blocks ---------------
    __syncthreads();
    if (tid == 0) {
        __threadfence();
        int old = atomicAdd(&g_done, 1);
        if (old == (int)gridDim.x - 1) {
            __threadfence();
            float tot = *((volatile float*)&g_accum);
            out[0] = tot / (float)B;
            *((volatile float*)&g_accum) = 0.f;
            __threadfence();
            *((volatile int*)&g_done) = 0;
        }
    }
}

extern "C" void kernel_launch(void* const* d_in, const int* in_sizes, int n_in,
                              void* d_out, int out_size)
{
    const float* feats   = (const float*)d_in[0];
    const float* trans   = (const float*)d_in[1];
    const int*   tags    = (const int*)d_in[2];
    const int*   lengths = (const int*)d_in[3];

    int B = in_sizes[3];
    int T = in_sizes[2] / B;
    int C = (T + NCH - 1) / NCH;

    crf_kernel<<<2 * B, 128>>>(feats, trans, tags, lengths,
                               (float*)d_out, B, T, C);
}